// round 15
// baseline (speedup 1.0000x reference)
#include <cuda_runtime.h>
#include <math.h>

// ---------------- constants ----------------
constexpr int Bc = 8, Tc = 2048, Ec = 256, Hc = 2, HDc = 128, M2c = 134;
constexpr int BT = Bc * Tc;            // 16384 rows
constexpr int QT = 64, KT = 64;        // attention tile sizes (2 CTAs/SM)
constexpr int NQT = Tc / QT;           // 32 q-tiles
constexpr int P = 132;                 // attn Q/K/V smem pitch
constexpr int SP = 68;                 // attn S smem pitch (68%32==4: conflict-free)
constexpr int GP = 68;                 // gemm A smem pitch
constexpr int GPW = 72;                // gemm W smem pitch (LDS.64 conflict-free)

// tf32 helpers
__device__ __forceinline__ unsigned f2tf(float f) {
    unsigned u; asm("cvt.rna.tf32.f32 %0, %1;" : "=r"(u) : "f"(f)); return u;
}
__device__ __forceinline__ void mma8(float c[4], const unsigned a[4], const unsigned b[2]) {
    asm volatile("mma.sync.aligned.m16n8k8.row.col.f32.tf32.tf32.f32 "
        "{%0,%1,%2,%3},{%4,%5,%6,%7},{%8,%9},{%0,%1,%2,%3};"
        : "+f"(c[0]), "+f"(c[1]), "+f"(c[2]), "+f"(c[3])
        : "r"(a[0]), "r"(a[1]), "r"(a[2]), "r"(a[3]), "r"(b[0]), "r"(b[1]));
}

// ---------------- scratch (device globals; no allocations allowed) --------
__device__ float g_x[BT * Ec];
__device__ float g_h[BT * Ec];
__device__ float g_qkv[BT * 3 * Ec];
__device__ float g_y[BT * Ec];
__device__ float g_fc[BT * 2 * Ec];
__device__ float g_part[64 * Ec];
__device__ unsigned g_wtf[524288];     // tf32+permuted weights: wq|wp|wf|wm
constexpr int WQo = 0;                 // 768*256
constexpr int WPo = 196608;            // 256*256
constexpr int WFo = 262144;            // 512*256
constexpr int WMo = 393216;            // 256*512

// ---------------- weight convert + permute (once per launch) ---------------
__global__ void convert_w_kernel(const float* __restrict__ wq,
                                 const float* __restrict__ wp,
                                 const float* __restrict__ wf,
                                 const float* __restrict__ wm,
                                 unsigned* __restrict__ out) {
    int idx = blockIdx.x * 256 + threadIdx.x;   // 0..524287
    const float* src; int rel, K;
    if (idx < WPo)      { src = wq; rel = idx;       K = 256; }
    else if (idx < WFo) { src = wp; rel = idx - WPo; K = 256; }
    else if (idx < WMo) { src = wf; rel = idx - WFo; K = 256; }
    else                { src = wm; rel = idx - WMo; K = 512; }
    int row = rel / K, col = rel % K;
    int kg = col >> 3, p = col & 7;
    int oldcol = (kg << 3) + (p >> 1) + ((p & 1) << 2);
    out[idx] = f2tf(src[row * K + oldcol]);
}

// ---------------- fused embed + ln1 ----------------
__global__ void embed_ln_kernel(const float* __restrict__ X,
                                const float* __restrict__ wpe,
                                const float* __restrict__ g,
                                const float* __restrict__ b,
                                float* __restrict__ xo,
                                float* __restrict__ ho) {
    int row = blockIdx.x;
    int t = row & (Tc - 1);
    int tid = threadIdx.x;
    __shared__ float rb[8];
    float v = X[row * Ec + tid] + wpe[t * Ec + tid]
            + wpe[(t >= Tc / 2 ? 1 : 0) * Ec + tid];
    v = fmaxf(v, 0.f);
    xo[row * Ec + tid] = v;

    float s = v;
    #pragma unroll
    for (int o = 16; o; o >>= 1) s += __shfl_xor_sync(~0u, s, o);
    if ((tid & 31) == 0) rb[tid >> 5] = s;
    __syncthreads();
    float tot = 0;
    #pragma unroll
    for (int i = 0; i < 8; i++) tot += rb[i];
    float mu = tot * (1.f / Ec);
    float d = v - mu;
    float s2 = d * d;
    #pragma unroll
    for (int o = 16; o; o >>= 1) s2 += __shfl_xor_sync(~0u, s2, o);
    __syncthreads();
    if ((tid & 31) == 0) rb[tid >> 5] = s2;
    __syncthreads();
    float tot2 = 0;
    #pragma unroll
    for (int i = 0; i < 8; i++) tot2 += rb[i];
    float r = rsqrtf(tot2 * (1.f / Ec) + 1e-5f);
    ho[row * Ec + tid] = d * r * g[tid] + b[tid];
}

// ---------------- layernorm ----------------
__global__ void ln_kernel(const float* __restrict__ in,
                          const float* __restrict__ g,
                          const float* __restrict__ b,
                          float* __restrict__ out, int relu_out) {
    int row = blockIdx.x;
    int tid = threadIdx.x;
    __shared__ float rb[8];
    float v = in[row * Ec + tid];
    float s = v;
    #pragma unroll
    for (int o = 16; o; o >>= 1) s += __shfl_xor_sync(~0u, s, o);
    if ((tid & 31) == 0) rb[tid >> 5] = s;
    __syncthreads();
    float tot = 0;
    #pragma unroll
    for (int i = 0; i < 8; i++) tot += rb[i];
    float mu = tot * (1.f / Ec);
    float d = v - mu;
    float s2 = d * d;
    #pragma unroll
    for (int o = 16; o; o >>= 1) s2 += __shfl_xor_sync(~0u, s2, o);
    __syncthreads();
    if ((tid & 31) == 0) rb[tid >> 5] = s2;
    __syncthreads();
    float tot2 = 0;
    #pragma unroll
    for (int i = 0; i < 8; i++) tot2 += rb[i];
    float r = rsqrtf(tot2 * (1.f / Ec) + 1e-5f);
    float o = d * r * g[tid] + b[tid];
    if (relu_out) o = fmaxf(o, 0.f);
    out[row * Ec + tid] = o;
}

// ---------------- GEMM (tf32, 2 CTAs/SM, permuted-W LDS.64) ---------------
constexpr int GEMM_SMEM = (128 * GP + 128 * GPW) * 4;   // 71680 B

__global__ void __launch_bounds__(256, 2)
gemm_tc_kernel(const float* __restrict__ A, const unsigned* __restrict__ Wp,
               const float* __restrict__ bias, const float* __restrict__ res,
               float* __restrict__ C, int M, int N, int K, int relu, int addres) {
    extern __shared__ unsigned gsm[];
    unsigned* As = gsm;                 // [128][GP]
    unsigned* Ws = gsm + 128 * GP;      // [128][GPW]

    int tid = threadIdx.x;
    int lane = tid & 31, wid = tid >> 5;
    int g = lane >> 2, tig = lane & 3;
    int wm = wid >> 1, wn = wid & 1;
    int bm = blockIdx.y * 128, bn = blockIdx.x * 128;

    float acc[2][8][4];
    #pragma unroll
    for (int ma = 0; ma < 2; ma++)
        #pragma unroll
        for (int na = 0; na < 8; na++)
            #pragma unroll
            for (int r = 0; r < 4; r++) acc[ma][na][r] = 0.f;

    for (int k0 = 0; k0 < K; k0 += 64) {
        __syncthreads();
        #pragma unroll
        for (int i = 0; i < 8; i++) {
            int idx = i * 256 + tid;
            int c4 = idx & 15, r = idx >> 4;
            float4 va = *(const float4*)(A + (long)(bm + r) * K + k0 + c4 * 4);
            *(uint4*)(As + r * GP + c4 * 4) =
                make_uint4(f2tf(va.x), f2tf(va.y), f2tf(va.z), f2tf(va.w));
            uint4 vw = *(const uint4*)(Wp + (long)(bn + r) * K + k0 + c4 * 4);
            *(uint4*)(Ws + r * GPW + c4 * 4) = vw;
        }
        __syncthreads();

        #pragma unroll
        for (int ks = 0; ks < 8; ks++) {
            int d0 = ks * 8;
            unsigned a[2][4];
            #pragma unroll
            for (int ma = 0; ma < 2; ma++) {
                int mr = wm * 32 + ma * 16;
                a[ma][0] = As[(mr + g) * GP + d0 + tig];
                a[ma][1] = As[(mr + g + 8) * GP + d0 + tig];
                a[ma][2] = As[(mr + g) * GP + d0 + tig + 4];
                a[ma][3] = As[(mr + g + 8) * GP + d0 + tig + 4];
            }
            #pragma unroll
            for (int na = 0; na < 8; na++) {
                int nc = wn * 64 + na * 8 + g;
                unsigned long long bb =
                    *(const unsigned long long*)(Ws + nc * GPW + d0 + 2 * tig);
                unsigned b[2] = { (unsigned)bb, (unsigned)(bb >> 32) };
                mma8(acc[0][na], a[0], b);
                mma8(acc[1][na], a[1], b);
            }
        }
    }

    #pragma unroll
    for (int ma = 0; ma < 2; ma++)
        #pragma unroll
        for (int na = 0; na < 8; na++) {
            int row0 = bm + wm * 32 + ma * 16 + g;
            int col  = bn + wn * 64 + na * 8 + 2 * tig;
            float* c = acc[ma][na];
            float b0 = bias[col], b1 = bias[col + 1];
            float v0 = c[0] + b0, v1 = c[1] + b1;
            float v2 = c[2] + b0, v3 = c[3] + b1;
            if (addres) {
                float2 r0 = *(const float2*)(res + (long)row0 * N + col);
                float2 r1 = *(const float2*)(res + (long)(row0 + 8) * N + col);
                v0 += r0.x; v1 += r0.y; v2 += r1.x; v3 += r1.y;
            }
            if (relu) {
                v0 = fmaxf(v0, 0.f); v1 = fmaxf(v1, 0.f);
                v2 = fmaxf(v2, 0.f); v3 = fmaxf(v3, 0.f);
            }
            *(float2*)(C + (long)row0 * N + col)       = make_float2(v0, v1);
            *(float2*)(C + (long)(row0 + 8) * N + col) = make_float2(v2, v3);
        }
}

// ---------------- attention: tf32 mma.sync, 64x64 tiles, 2 CTAs/SM --------
// 8 warps: wm = wid>>1 (4 q-strips of 16), wn = wid&1 (2 col-strips).
constexpr int ATTN_SMEM = 3 * 64 * P * 4;   // 101376 B -> 2 CTAs/SM

__device__ __forceinline__ void load_tile64_tf32(const float* __restrict__ src,
                                                 unsigned* dst, int tid) {
    #pragma unroll
    for (int i = 0; i < 8; i++) {
        int idx = i * 256 + tid;
        int d4 = idx & 31, r = idx >> 5;   // r 0..63
        float4 v = *(const float4*)(src + (long)r * 768 + d4 * 4);
        uint4 u = make_uint4(f2tf(v.x), f2tf(v.y), f2tf(v.z), f2tf(v.w));
        *(uint4*)(dst + r * P + d4 * 4) = u;
    }
}

__device__ __forceinline__ void attn_tile(const float* __restrict__ qkv,
                                          float* __restrict__ y,
                                          unsigned* Qs, unsigned* Ks, unsigned* Vs,
                                          int qt, int baserow, int h, int tid) {
    const float scale = 0.08838834764831845f;   // 1/sqrt(128)
    int lane = tid & 31, wid = tid >> 5;
    int g = lane >> 2, tig = lane & 3;
    int wm = wid >> 1, wn = wid & 1;
    unsigned* Ss = Ks;   // alias: S[64][SP]=17408B fits in K's 64*P=33792B

    load_tile64_tf32(qkv + (long)(baserow + qt * QT) * 768 + h * HDc, Qs, tid);

    float yacc[8][4];    // q rows wm*16+g(+8); d cols wn*64 + na*8
    #pragma unroll
    for (int na = 0; na < 8; na++)
        #pragma unroll
        for (int r = 0; r < 4; r++) yacc[na][r] = 0.f;

    for (int kt = 0; kt <= qt; kt++) {
        __syncthreads();   // prev AV reads of Ss/Vs done; Qs visible (1st iter)
        const float* kvb = qkv + (long)(baserow + kt * KT) * 768 + h * HDc;
        load_tile64_tf32(kvb + 256, Ks, tid);
        load_tile64_tf32(kvb + 512, Vs, tid);
        __syncthreads();

        // ---- S = Q @ K^T : per warp rows wm*16..+15, cols wn*32 + na*8 ----
        float sacc[4][4];
        #pragma unroll
        for (int na = 0; na < 4; na++)
            #pragma unroll
            for (int r = 0; r < 4; r++) sacc[na][r] = 0.f;

        #pragma unroll 4
        for (int ks = 0; ks < 16; ks++) {
            int d0 = ks * 8;
            int qr = wm * 16;
            unsigned a[4];
            a[0] = Qs[(qr + g) * P + d0 + tig];
            a[1] = Qs[(qr + g + 8) * P + d0 + tig];
            a[2] = Qs[(qr + g) * P + d0 + tig + 4];
            a[3] = Qs[(qr + g + 8) * P + d0 + tig + 4];
            #pragma unroll
            for (int na = 0; na < 4; na++) {
                int kc = wn * 32 + na * 8 + g;
                unsigned b[2] = { Ks[kc * P + d0 + tig], Ks[kc * P + d0 + tig + 4] };
                mma8(sacc[na], a, b);
            }
        }
        __syncthreads();   // all Ks reads done; Ss may overwrite

        #pragma unroll
        for (int na = 0; na < 4; na++) {
            int lq0 = wm * 16 + g;
            int lk  = wn * 32 + na * 8 + 2 * tig;
            int qg0 = qt * QT + lq0, qg1 = qg0 + 8;
            int kg  = kt * KT + lk;
            float* c = sacc[na];
            float v0 = (kg     <= qg0) ? fmaxf(c[0] * scale, 0.f) : 0.f;
            float v1 = (kg + 1 <= qg0) ? fmaxf(c[1] * scale, 0.f) : 0.f;
            float v2 = (kg     <= qg1) ? fmaxf(c[2] * scale, 0.f) : 0.f;
            float v3 = (kg + 1 <= qg1) ? fmaxf(c[3] * scale, 0.f) : 0.f;
            *(uint2*)(Ss + lq0 * SP + lk)       = make_uint2(f2tf(v0), f2tf(v1));
            *(uint2*)(Ss + (lq0 + 8) * SP + lk) = make_uint2(f2tf(v2), f2tf(v3));
        }
        __syncthreads();   // Ss visible

        // ---- Y += S @ V : per warp rows wm*16.., d cols wn*64 + na*8 ----
        #pragma unroll
        for (int ks = 0; ks < 8; ks++) {
            int kp0 = ks * 8;
            int qr = wm * 16;
            unsigned a[4];
            a[0] = Ss[(qr + g) * SP + kp0 + tig];
            a[1] = Ss[(qr + g + 8) * SP + kp0 + tig];
            a[2] = Ss[(qr + g) * SP + kp0 + tig + 4];
            a[3] = Ss[(qr + g + 8) * SP + kp0 + tig + 4];
            #pragma unroll
            for (int na = 0; na < 8; na++) {
                int dc = wn * 64 + na * 8 + g;
                unsigned b[2] = { Vs[(kp0 + tig) * P + dc], Vs[(kp0 + tig + 4) * P + dc] };
                mma8(yacc[na], a, b);
            }
        }
    }

    #pragma unroll
    for (int na = 0; na < 8; na++) {
        int row0 = baserow + qt * QT + wm * 16 + g;
        int col  = h * HDc + wn * 64 + na * 8 + 2 * tig;
        float* c = yacc[na];
        *(float2*)(y + (long)row0 * Ec + col)       = make_float2(c[0], c[1]);
        *(float2*)(y + (long)(row0 + 8) * Ec + col) = make_float2(c[2], c[3]);
    }
}

__global__ void __launch_bounds__(256, 2)
attn_kernel(const float* __restrict__ qkv, float* __restrict__ y) {
    extern __shared__ unsigned smu[];
    unsigned* Qs = smu;
    unsigned* Ks = smu + 64 * P;
    unsigned* Vs = smu + 2 * 64 * P;

    int pair = blockIdx.x;     // 0..NQT/2-1
    int bh = blockIdx.y;
    int b = bh >> 1, h = bh & 1;
    int baserow = b * Tc;

    // heavy tile then light tile: uniform 33 k-iterations per block
    attn_tile(qkv, y, Qs, Ks, Vs, NQT - 1 - pair, baserow, h, threadIdx.x);
    __syncthreads();
    attn_tile(qkv, y, Qs, Ks, Vs, pair, baserow, h, threadIdx.x);
}

// ---------------- mean over T ----------------
__global__ void meanpart_kernel(const float* __restrict__ xf, float* __restrict__ part) {
    int c = blockIdx.x;
    int b = blockIdx.y;
    int e = threadIdx.x;
    float s = 0.f;
    for (int tt = 0; tt < 256; tt++) {
        int t = c * 256 + tt;
        s += xf[(b * Tc + t) * Ec + e];
    }
    part[(c * Bc + b) * Ec + e] = s;
}

// ---------------- final (1024 threads) ----------------
__global__ void __launch_bounds__(1024)
final_kernel(const float* __restrict__ part,
             const float* __restrict__ head_w,
             const float* __restrict__ head_b,
             const float* __restrict__ Y,
             float* __restrict__ out) {
    __shared__ float emb[Bc * Ec];
    __shared__ float lg[Bc * M2c];
    __shared__ float rb[32];
    int tid = threadIdx.x;

    for (int i = tid; i < Bc * Ec; i += 1024) {
        int b = i >> 8, e = i & 255;
        float s = 0.f;
        #pragma unroll
        for (int c = 0; c < 8; c++) s += part[(c * Bc + b) * Ec + e];
        emb[i] = s * (1.f / Tc);
    }
    __syncthreads();

    float l1 = 0.f;
    for (int o = tid; o < Bc * M2c; o += 1024) {
        int b = o / M2c, m = o % M2c;
        float s = head_b[m];
        const float* wr = head_w + m * Ec;
        const float* er = emb + b * Ec;
        #pragma unroll 4
        for (int k = 0; k < Ec; k++) s += er[k] * wr[k];
        s = fmaxf(s, 0.f);
        lg[o] = s;
        float d = s - Y[o];
        l1 += d * d;
    }
    #pragma unroll
    for (int o = 16; o; o >>= 1) l1 += __shfl_xor_sync(~0u, l1, o);
    if ((tid & 31) == 0) rb[tid >> 5] = l1;
    __syncthreads();
    float tot1 = 0.f;
    #pragma unroll
    for (int i = 0; i < 32; i++) tot1 += rb[i];
    float loss1 = sqrtf(tot1 / (float)(Bc * M2c));
    __syncthreads();

    float l3 = 0.f;
    for (int i = tid; i < Bc * (Ec / 2); i += 1024) {
        int b = i / (Ec / 2), j = i % (Ec / 2);
        float e1 = emb[b * Ec + j];
        float e2 = emb[b * Ec + Ec / 2 + j];
        out[i] = e1;
        out[Bc * (Ec / 2) + i] = e2;
        float d = e1 - e2;
        l3 += d * d;
    }
    #pragma unroll
    for (int o = 16; o; o >>= 1) l3 += __shfl_xor_sync(~0u, l3, o);
    if ((tid & 31) == 0) rb[tid >> 5] = l3;
    __syncthreads();
    float tot3 = 0.f;
    #pragma unroll
    for (int i = 0; i < 32; i++) tot3 += rb[i];
    float loss3 = sqrtf(tot3 / (float)(Bc * Ec / 2));

    int off = 2 * Bc * (Ec / 2);
    if (tid == 0) {
        out[off + 0] = 50.f * loss1 + loss3;
        out[off + 1] = loss1;
        out[off + 2] = loss3;
    }
    for (int o = tid; o < Bc * M2c; o += 1024) out[off + 3 + o] = lg[o];
}

// ---------------- host launcher ----------------
extern "C" void kernel_launch(void* const* d_in, const int* in_sizes, int n_in,
                              void* d_out, int out_size) {
    const float* X          = (const float*)d_in[0];
    const float* Y          = (const float*)d_in[1];
    const float* wpe        = (const float*)d_in[2];
    const float* ln1_g      = (const float*)d_in[3];
    const float* ln1_b      = (const float*)d_in[4];
    const float* attn_w     = (const float*)d_in[5];
    const float* attn_b     = (const float*)d_in[6];
    const float* attnproj_w = (const float*)d_in[7];
    const float* attnproj_b = (const float*)d_in[8];
    const float* ln2_g      = (const float*)d_in[9];
    const float* ln2_b      = (const float*)d_in[10];
    const float* fc_w       = (const float*)d_in[11];
    const float* fc_b       = (const float*)d_in[12];
    const float* mlpproj_w  = (const float*)d_in[13];
    const float* mlpproj_b  = (const float*)d_in[14];
    const float* lnf_g      = (const float*)d_in[15];
    const float* lnf_b      = (const float*)d_in[16];
    const float* head_w     = (const float*)d_in[17];
    const float* head_b     = (const float*)d_in[18];

    float *x, *h, *qkv, *y, *fc, *part;
    unsigned* wtf;
    cudaGetSymbolAddress((void**)&x, g_x);
    cudaGetSymbolAddress((void**)&h, g_h);
    cudaGetSymbolAddress((void**)&qkv, g_qkv);
    cudaGetSymbolAddress((void**)&y, g_y);
    cudaGetSymbolAddress((void**)&fc, g_fc);
    cudaGetSymbolAddress((void**)&part, g_part);
    cudaGetSymbolAddress((void**)&wtf, g_wtf);

    cudaFuncSetAttribute(attn_kernel, cudaFuncAttributeMaxDynamicSharedMemorySize, ATTN_SMEM);
    cudaFuncSetAttribute(attn_kernel, cudaFuncAttributePreferredSharedMemoryCarveout,
                         cudaSharedmemCarveoutMaxShared);
    cudaFuncSetAttribute(gemm_tc_kernel, cudaFuncAttributeMaxDynamicSharedMemorySize, GEMM_SMEM);
    cudaFuncSetAttribute(gemm_tc_kernel, cudaFuncAttributePreferredSharedMemoryCarveout,
                         cudaSharedmemCarveoutMaxShared);

    convert_w_kernel<<<2048, 256>>>(attn_w, attnproj_w, fc_w, mlpproj_w, wtf);
    embed_ln_kernel<<<BT, 256>>>(X, wpe, ln1_g, ln1_b, x, h);
    gemm_tc_kernel<<<dim3(6, 128), 256, GEMM_SMEM>>>(h, wtf + WQo, attn_b, nullptr, qkv, BT, 768, 256, 1, 0);
    attn_kernel<<<dim3(NQT / 2, Bc * Hc), 256, ATTN_SMEM>>>(qkv, y);
    gemm_tc_kernel<<<dim3(2, 128), 256, GEMM_SMEM>>>(y, wtf + WPo, attnproj_b, x, x, BT, 256, 256, 0, 1);
    ln_kernel<<<BT, 256>>>(x, ln2_g, ln2_b, h, 0);
    gemm_tc_kernel<<<dim3(4, 128), 256, GEMM_SMEM>>>(h, wtf + WFo, fc_b, nullptr, fc, BT, 512, 256, 1, 0);
    gemm_tc_kernel<<<dim3(2, 128), 256, GEMM_SMEM>>>(fc, wtf + WMo, mlpproj_b, x, x, BT, 256, 512, 1, 1);
    ln_kernel<<<BT, 256>>>(x, lnf_g, lnf_b, h, 1);
    meanpart_kernel<<<dim3(8, Bc), 256>>>(h, part);
    final_kernel<<<1, 1024>>>(part, head_w, head_b, Y, (float*)d_out);
}

// round 16
// speedup vs baseline: 1.1928x; 1.1928x over previous
#include <cuda_runtime.h>
#include <math.h>

// ---------------- constants ----------------
constexpr int Bc = 8, Tc = 2048, Ec = 256, Hc = 2, HDc = 128, M2c = 134;
constexpr int BT = Bc * Tc;            // 16384 rows
constexpr int QT2 = 128, KT2 = 128;    // attention tile sizes
constexpr int NQT2 = Tc / QT2;         // 16 q-tiles
constexpr int P = 132;                 // attn smem pitch
constexpr int GP = 68;                 // gemm A smem pitch
constexpr int GPW = 72;                // gemm W smem pitch (LDS.64 conflict-free)

// tf32 helpers
__device__ __forceinline__ unsigned f2tf(float f) {
    unsigned u; asm("cvt.rna.tf32.f32 %0, %1;" : "=r"(u) : "f"(f)); return u;
}
__device__ __forceinline__ void mma8(float c[4], const unsigned a[4], const unsigned b[2]) {
    asm volatile("mma.sync.aligned.m16n8k8.row.col.f32.tf32.tf32.f32 "
        "{%0,%1,%2,%3},{%4,%5,%6,%7},{%8,%9},{%0,%1,%2,%3};"
        : "+f"(c[0]), "+f"(c[1]), "+f"(c[2]), "+f"(c[3])
        : "r"(a[0]), "r"(a[1]), "r"(a[2]), "r"(a[3]), "r"(b[0]), "r"(b[1]));
}
__device__ __forceinline__ float wredsum(float v) {
    #pragma unroll
    for (int o = 16; o; o >>= 1) v += __shfl_xor_sync(~0u, v, o);
    return v;
}

// ---------------- scratch (device globals; no allocations allowed) --------
__device__ float g_x[BT * Ec];
__device__ float g_h[BT * Ec];
__device__ float g_qkv[BT * 3 * Ec];
__device__ float g_y[BT * Ec];
__device__ float g_fc[BT * 2 * Ec];
__device__ float g_part[64 * Ec];
__device__ unsigned g_wtf[524288];     // tf32+permuted weights: wq|wp|wf|wm
constexpr int WQo = 0;                 // 768*256
constexpr int WPo = 196608;            // 256*256
constexpr int WFo = 262144;            // 512*256
constexpr int WMo = 393216;            // 256*512

// ---------------- weight convert + permute (once per launch) ---------------
__global__ void convert_w_kernel(const float* __restrict__ wq,
                                 const float* __restrict__ wp,
                                 const float* __restrict__ wf,
                                 const float* __restrict__ wm,
                                 unsigned* __restrict__ out) {
    int idx = blockIdx.x * 256 + threadIdx.x;   // 0..524287
    const float* src; int rel, K;
    if (idx < WPo)      { src = wq; rel = idx;       K = 256; }
    else if (idx < WFo) { src = wp; rel = idx - WPo; K = 256; }
    else if (idx < WMo) { src = wf; rel = idx - WFo; K = 256; }
    else                { src = wm; rel = idx - WMo; K = 512; }
    int row = rel / K, col = rel % K;
    int kg = col >> 3, p = col & 7;
    int oldcol = (kg << 3) + (p >> 1) + ((p & 1) << 2);
    out[idx] = f2tf(src[row * K + oldcol]);
}

// ---------------- fused embed + ln1 (warp per row, 8 rows/block) ----------
__global__ void embed_ln_kernel(const float* __restrict__ X,
                                const float* __restrict__ wpe,
                                const float* __restrict__ g,
                                const float* __restrict__ b,
                                float* __restrict__ xo,
                                float* __restrict__ ho) {
    int row = blockIdx.x * 8 + (threadIdx.x >> 5);
    int lane = threadIdx.x & 31;
    int t = row & (Tc - 1);
    int cls = (t >= Tc / 2) ? 1 : 0;
    int e0 = lane * 4, e1 = 128 + lane * 4;

    float4 a0 = *(const float4*)(X + (long)row * Ec + e0);
    float4 a1 = *(const float4*)(X + (long)row * Ec + e1);
    float4 w0 = *(const float4*)(wpe + (long)t * Ec + e0);
    float4 w1 = *(const float4*)(wpe + (long)t * Ec + e1);
    float4 c0 = *(const float4*)(wpe + (long)cls * Ec + e0);
    float4 c1 = *(const float4*)(wpe + (long)cls * Ec + e1);
    float v[8] = {
        fmaxf(a0.x + w0.x + c0.x, 0.f), fmaxf(a0.y + w0.y + c0.y, 0.f),
        fmaxf(a0.z + w0.z + c0.z, 0.f), fmaxf(a0.w + w0.w + c0.w, 0.f),
        fmaxf(a1.x + w1.x + c1.x, 0.f), fmaxf(a1.y + w1.y + c1.y, 0.f),
        fmaxf(a1.z + w1.z + c1.z, 0.f), fmaxf(a1.w + w1.w + c1.w, 0.f) };
    *(float4*)(xo + (long)row * Ec + e0) = make_float4(v[0], v[1], v[2], v[3]);
    *(float4*)(xo + (long)row * Ec + e1) = make_float4(v[4], v[5], v[6], v[7]);

    float s = 0.f;
    #pragma unroll
    for (int i = 0; i < 8; i++) s += v[i];
    s = wredsum(s);
    float mu = s * (1.f / Ec);
    float s2 = 0.f;
    #pragma unroll
    for (int i = 0; i < 8; i++) { float d = v[i] - mu; s2 += d * d; }
    s2 = wredsum(s2);
    float r = rsqrtf(s2 * (1.f / Ec) + 1e-5f);

    float4 g0 = *(const float4*)(g + e0), g1 = *(const float4*)(g + e1);
    float4 b0 = *(const float4*)(b + e0), b1 = *(const float4*)(b + e1);
    float4 o0 = make_float4((v[0] - mu) * r * g0.x + b0.x, (v[1] - mu) * r * g0.y + b0.y,
                            (v[2] - mu) * r * g0.z + b0.z, (v[3] - mu) * r * g0.w + b0.w);
    float4 o1 = make_float4((v[4] - mu) * r * g1.x + b1.x, (v[5] - mu) * r * g1.y + b1.y,
                            (v[6] - mu) * r * g1.z + b1.z, (v[7] - mu) * r * g1.w + b1.w);
    *(float4*)(ho + (long)row * Ec + e0) = o0;
    *(float4*)(ho + (long)row * Ec + e1) = o1;
}

// ---------------- layernorm (warp per row, 8 rows/block) ------------------
__global__ void ln_kernel(const float* __restrict__ in,
                          const float* __restrict__ g,
                          const float* __restrict__ b,
                          float* __restrict__ out, int relu_out) {
    int row = blockIdx.x * 8 + (threadIdx.x >> 5);
    int lane = threadIdx.x & 31;
    int e0 = lane * 4, e1 = 128 + lane * 4;

    float4 a0 = *(const float4*)(in + (long)row * Ec + e0);
    float4 a1 = *(const float4*)(in + (long)row * Ec + e1);
    float v[8] = { a0.x, a0.y, a0.z, a0.w, a1.x, a1.y, a1.z, a1.w };

    float s = 0.f;
    #pragma unroll
    for (int i = 0; i < 8; i++) s += v[i];
    s = wredsum(s);
    float mu = s * (1.f / Ec);
    float s2 = 0.f;
    #pragma unroll
    for (int i = 0; i < 8; i++) { float d = v[i] - mu; s2 += d * d; }
    s2 = wredsum(s2);
    float r = rsqrtf(s2 * (1.f / Ec) + 1e-5f);

    float4 g0 = *(const float4*)(g + e0), g1 = *(const float4*)(g + e1);
    float4 b0 = *(const float4*)(b + e0), b1 = *(const float4*)(b + e1);
    float o[8];
    o[0] = (v[0] - mu) * r * g0.x + b0.x; o[1] = (v[1] - mu) * r * g0.y + b0.y;
    o[2] = (v[2] - mu) * r * g0.z + b0.z; o[3] = (v[3] - mu) * r * g0.w + b0.w;
    o[4] = (v[4] - mu) * r * g1.x + b1.x; o[5] = (v[5] - mu) * r * g1.y + b1.y;
    o[6] = (v[6] - mu) * r * g1.z + b1.z; o[7] = (v[7] - mu) * r * g1.w + b1.w;
    if (relu_out) {
        #pragma unroll
        for (int i = 0; i < 8; i++) o[i] = fmaxf(o[i], 0.f);
    }
    *(float4*)(out + (long)row * Ec + e0) = make_float4(o[0], o[1], o[2], o[3]);
    *(float4*)(out + (long)row * Ec + e1) = make_float4(o[4], o[5], o[6], o[7]);
}

// ---------------- GEMM (tf32, 2 CTAs/SM, permuted-W LDS.64) ---------------
constexpr int GEMM_SMEM = (128 * GP + 128 * GPW) * 4;   // 71680 B

__global__ void __launch_bounds__(256, 2)
gemm_tc_kernel(const float* __restrict__ A, const unsigned* __restrict__ Wp,
               const float* __restrict__ bias, const float* __restrict__ res,
               float* __restrict__ C, int M, int N, int K, int relu, int addres) {
    extern __shared__ unsigned gsm[];
    unsigned* As = gsm;                 // [128][GP]
    unsigned* Ws = gsm + 128 * GP;      // [128][GPW]

    int tid = threadIdx.x;
    int lane = tid & 31, wid = tid >> 5;
    int g = lane >> 2, tig = lane & 3;
    int wm = wid >> 1, wn = wid & 1;
    int bm = blockIdx.y * 128, bn = blockIdx.x * 128;

    float acc[2][8][4];
    #pragma unroll
    for (int ma = 0; ma < 2; ma++)
        #pragma unroll
        for (int na = 0; na < 8; na++)
            #pragma unroll
            for (int r = 0; r < 4; r++) acc[ma][na][r] = 0.f;

    for (int k0 = 0; k0 < K; k0 += 64) {
        __syncthreads();
        #pragma unroll
        for (int i = 0; i < 8; i++) {
            int idx = i * 256 + tid;
            int c4 = idx & 15, r = idx >> 4;
            float4 va = *(const float4*)(A + (long)(bm + r) * K + k0 + c4 * 4);
            *(uint4*)(As + r * GP + c4 * 4) =
                make_uint4(f2tf(va.x), f2tf(va.y), f2tf(va.z), f2tf(va.w));
            uint4 vw = *(const uint4*)(Wp + (long)(bn + r) * K + k0 + c4 * 4);
            *(uint4*)(Ws + r * GPW + c4 * 4) = vw;
        }
        __syncthreads();

        #pragma unroll
        for (int ks = 0; ks < 8; ks++) {
            int d0 = ks * 8;
            unsigned a[2][4];
            #pragma unroll
            for (int ma = 0; ma < 2; ma++) {
                int mr = wm * 32 + ma * 16;
                a[ma][0] = As[(mr + g) * GP + d0 + tig];
                a[ma][1] = As[(mr + g + 8) * GP + d0 + tig];
                a[ma][2] = As[(mr + g) * GP + d0 + tig + 4];
                a[ma][3] = As[(mr + g + 8) * GP + d0 + tig + 4];
            }
            #pragma unroll
            for (int na = 0; na < 8; na++) {
                int nc = wn * 64 + na * 8 + g;
                unsigned long long bb =
                    *(const unsigned long long*)(Ws + nc * GPW + d0 + 2 * tig);
                unsigned b[2] = { (unsigned)bb, (unsigned)(bb >> 32) };
                mma8(acc[0][na], a[0], b);
                mma8(acc[1][na], a[1], b);
            }
        }
    }

    #pragma unroll
    for (int ma = 0; ma < 2; ma++)
        #pragma unroll
        for (int na = 0; na < 8; na++) {
            int row0 = bm + wm * 32 + ma * 16 + g;
            int col  = bn + wn * 64 + na * 8 + 2 * tig;
            float* c = acc[ma][na];
            float b0 = bias[col], b1 = bias[col + 1];
            float v0 = c[0] + b0, v1 = c[1] + b1;
            float v2 = c[2] + b0, v3 = c[3] + b1;
            if (addres) {
                float2 r0 = *(const float2*)(res + (long)row0 * N + col);
                float2 r1 = *(const float2*)(res + (long)(row0 + 8) * N + col);
                v0 += r0.x; v1 += r0.y; v2 += r1.x; v3 += r1.y;
            }
            if (relu) {
                v0 = fmaxf(v0, 0.f); v1 = fmaxf(v1, 0.f);
                v2 = fmaxf(v2, 0.f); v3 = fmaxf(v3, 0.f);
            }
            *(float2*)(C + (long)row0 * N + col)       = make_float2(v0, v1);
            *(float2*)(C + (long)(row0 + 8) * N + col) = make_float2(v2, v3);
        }
}

// ---------------- attention: tf32 mma.sync (R14 design, 128x128) ----------
constexpr int ATTN_SMEM = 3 * 128 * P * 4;   // 202752 B

__device__ __forceinline__ void load_tile_tf32(const float* __restrict__ src,
                                               unsigned* dst, int tid) {
    #pragma unroll
    for (int i = 0; i < 16; i++) {
        int idx = i * 256 + tid;
        int d4 = idx & 31, r = idx >> 5;
        float4 v = *(const float4*)(src + (long)r * 768 + d4 * 4);
        uint4 u = make_uint4(f2tf(v.x), f2tf(v.y), f2tf(v.z), f2tf(v.w));
        *(uint4*)(dst + r * P + d4 * 4) = u;
    }
}

__device__ __forceinline__ void attn_tile(const float* __restrict__ qkv,
                                          float* __restrict__ y,
                                          unsigned* Qs, unsigned* Ks, unsigned* Vs,
                                          int qt, int baserow, int h, int tid) {
    const float scale = 0.08838834764831845f;   // 1/sqrt(128)
    int lane = tid & 31, wid = tid >> 5;
    int g = lane >> 2, tig = lane & 3;
    int wm = wid >> 1, wn = wid & 1;
    unsigned* Ss = Ks;   // alias: S over K's region (dead after S phase)

    load_tile_tf32(qkv + (long)(baserow + qt * QT2) * 768 + h * HDc, Qs, tid);

    float yacc[2][8][4];
    #pragma unroll
    for (int ma = 0; ma < 2; ma++)
        #pragma unroll
        for (int na = 0; na < 8; na++)
            #pragma unroll
            for (int r = 0; r < 4; r++) yacc[ma][na][r] = 0.f;

    for (int kt = 0; kt <= qt; kt++) {
        __syncthreads();
        const float* kvb = qkv + (long)(baserow + kt * KT2) * 768 + h * HDc;
        load_tile_tf32(kvb + 256, Ks, tid);
        load_tile_tf32(kvb + 512, Vs, tid);
        __syncthreads();

        // ---- S = Q @ K^T ----
        float sacc[2][8][4];
        #pragma unroll
        for (int ma = 0; ma < 2; ma++)
            #pragma unroll
            for (int na = 0; na < 8; na++)
                #pragma unroll
                for (int r = 0; r < 4; r++) sacc[ma][na][r] = 0.f;

        #pragma unroll 4
        for (int ks = 0; ks < 16; ks++) {
            int d0 = ks * 8;
            unsigned a[2][4];
            #pragma unroll
            for (int ma = 0; ma < 2; ma++) {
                int qr = wm * 32 + ma * 16;
                a[ma][0] = Qs[(qr + g) * P + d0 + tig];
                a[ma][1] = Qs[(qr + g + 8) * P + d0 + tig];
                a[ma][2] = Qs[(qr + g) * P + d0 + tig + 4];
                a[ma][3] = Qs[(qr + g + 8) * P + d0 + tig + 4];
            }
            #pragma unroll
            for (int na = 0; na < 8; na++) {
                int kc = wn * 64 + na * 8 + g;
                unsigned b[2] = { Ks[kc * P + d0 + tig], Ks[kc * P + d0 + tig + 4] };
                mma8(sacc[0][na], a[0], b);
                mma8(sacc[1][na], a[1], b);
            }
        }
        __syncthreads();   // all Ks reads done; Ss may overwrite

        #pragma unroll
        for (int ma = 0; ma < 2; ma++)
            #pragma unroll
            for (int na = 0; na < 8; na++) {
                int lq0 = wm * 32 + ma * 16 + g;
                int lk  = wn * 64 + na * 8 + 2 * tig;
                int qg0 = qt * QT2 + lq0, qg1 = qg0 + 8;
                int kg  = kt * KT2 + lk;
                float* c = sacc[ma][na];
                float v0 = (kg     <= qg0) ? fmaxf(c[0] * scale, 0.f) : 0.f;
                float v1 = (kg + 1 <= qg0) ? fmaxf(c[1] * scale, 0.f) : 0.f;
                float v2 = (kg     <= qg1) ? fmaxf(c[2] * scale, 0.f) : 0.f;
                float v3 = (kg + 1 <= qg1) ? fmaxf(c[3] * scale, 0.f) : 0.f;
                *(uint2*)(Ss + lq0 * P + lk)       = make_uint2(f2tf(v0), f2tf(v1));
                *(uint2*)(Ss + (lq0 + 8) * P + lk) = make_uint2(f2tf(v2), f2tf(v3));
            }
        __syncthreads();   // Ss visible

        // ---- Y += S @ V ----
        #pragma unroll 4
        for (int ks = 0; ks < 16; ks++) {
            int kp0 = ks * 8;
            unsigned a[2][4];
            #pragma unroll
            for (int ma = 0; ma < 2; ma++) {
                int qr = wm * 32 + ma * 16;
                a[ma][0] = Ss[(qr + g) * P + kp0 + tig];
                a[ma][1] = Ss[(qr + g + 8) * P + kp0 + tig];
                a[ma][2] = Ss[(qr + g) * P + kp0 + tig + 4];
                a[ma][3] = Ss[(qr + g + 8) * P + kp0 + tig + 4];
            }
            #pragma unroll
            for (int na = 0; na < 8; na++) {
                int dc = wn * 64 + na * 8 + g;
                unsigned b[2] = { Vs[(kp0 + tig) * P + dc], Vs[(kp0 + tig + 4) * P + dc] };
                mma8(yacc[0][na], a[0], b);
                mma8(yacc[1][na], a[1], b);
            }
        }
    }

    #pragma unroll
    for (int ma = 0; ma < 2; ma++)
        #pragma unroll
        for (int na = 0; na < 8; na++) {
            int row0 = baserow + qt * QT2 + wm * 32 + ma * 16 + g;
            int col  = h * HDc + wn * 64 + na * 8 + 2 * tig;
            float* c = yacc[ma][na];
            *(float2*)(y + (long)row0 * Ec + col)       = make_float2(c[0], c[1]);
            *(float2*)(y + (long)(row0 + 8) * Ec + col) = make_float2(c[2], c[3]);
        }
}

__global__ void __launch_bounds__(256, 1)
attn_kernel(const float* __restrict__ qkv, float* __restrict__ y) {
    extern __shared__ unsigned smu[];
    unsigned* Qs = smu;
    unsigned* Ks = smu + 128 * P;
    unsigned* Vs = smu + 2 * 128 * P;

    int pair = blockIdx.x;
    int bh = blockIdx.y;
    int b = bh >> 1, h = bh & 1;
    int baserow = b * Tc;

    attn_tile(qkv, y, Qs, Ks, Vs, NQT2 - 1 - pair, baserow, h, threadIdx.x);
    __syncthreads();
    attn_tile(qkv, y, Qs, Ks, Vs, pair, baserow, h, threadIdx.x);
}

// ---------------- mean over T ----------------
__global__ void meanpart_kernel(const float* __restrict__ xf, float* __restrict__ part) {
    int c = blockIdx.x;
    int b = blockIdx.y;
    int e = threadIdx.x;
    float s = 0.f;
    for (int tt = 0; tt < 256; tt++) {
        int t = c * 256 + tt;
        s += xf[(b * Tc + t) * Ec + e];
    }
    part[(c * Bc + b) * Ec + e] = s;
}

// ---------------- final (1024 threads) ----------------
__global__ void __launch_bounds__(1024)
final_kernel(const float* __restrict__ part,
             const float* __restrict__ head_w,
             const float* __restrict__ head_b,
             const float* __restrict__ Y,
             float* __restrict__ out) {
    __shared__ float emb[Bc * Ec];
    __shared__ float lg[Bc * M2c];
    __shared__ float rb[32];
    int tid = threadIdx.x;

    for (int i = tid; i < Bc * Ec; i += 1024) {
        int b = i >> 8, e = i & 255;
        float s = 0.f;
        #pragma unroll
        for (int c = 0; c < 8; c++) s += part[(c * Bc + b) * Ec + e];
        emb[i] = s * (1.f / Tc);
    }
    __syncthreads();

    float l1 = 0.f;
    for (int o = tid; o < Bc * M2c; o += 1024) {
        int b = o / M2c, m = o % M2c;
        float s = head_b[m];
        const float* wr = head_w + m * Ec;
        const float* er = emb + b * Ec;
        #pragma unroll 4
        for (int k = 0; k < Ec; k++) s += er[k] * wr[k];
        s = fmaxf(s, 0.f);
        lg[o] = s;
        float d = s - Y[o];
        l1 += d * d;
    }
    l1 = wredsum(l1);
    if ((tid & 31) == 0) rb[tid >> 5] = l1;
    __syncthreads();
    float tot1 = 0.f;
    #pragma unroll
    for (int i = 0; i < 32; i++) tot1 += rb[i];
    float loss1 = sqrtf(tot1 / (float)(Bc * M2c));
    __syncthreads();

    float l3 = 0.f;
    for (int i = tid; i < Bc * (Ec / 2); i += 1024) {
        int b = i / (Ec / 2), j = i % (Ec / 2);
        float e1 = emb[b * Ec + j];
        float e2 = emb[b * Ec + Ec / 2 + j];
        out[i] = e1;
        out[Bc * (Ec / 2) + i] = e2;
        float d = e1 - e2;
        l3 += d * d;
    }
    l3 = wredsum(l3);
    if ((tid & 31) == 0) rb[tid >> 5] = l3;
    __syncthreads();
    float tot3 = 0.f;
    #pragma unroll
    for (int i = 0; i < 32; i++) tot3 += rb[i];
    float loss3 = sqrtf(tot3 / (float)(Bc * Ec / 2));

    int off = 2 * Bc * (Ec / 2);
    if (tid == 0) {
        out[off + 0] = 50.f * loss1 + loss3;
        out[off + 1] = loss1;
        out[off + 2] = loss3;
    }
    for (int o = tid; o < Bc * M2c; o += 1024) out[off + 3 + o] = lg[o];
}

// ---------------- host launcher ----------------
extern "C" void kernel_launch(void* const* d_in, const int* in_sizes, int n_in,
                              void* d_out, int out_size) {
    const float* X          = (const float*)d_in[0];
    const float* Y          = (const float*)d_in[1];
    const float* wpe        = (const float*)d_in[2];
    const float* ln1_g      = (const float*)d_in[3];
    const float* ln1_b      = (const float*)d_in[4];
    const float* attn_w     = (const float*)d_in[5];
    const float* attn_b     = (const float*)d_in[6];
    const float* attnproj_w = (const float*)d_in[7];
    const float* attnproj_b = (const float*)d_in[8];
    const float* ln2_g      = (const float*)d_in[9];
    const float* ln2_b      = (const float*)d_in[10];
    const float* fc_w       = (const float*)d_in[11];
    const float* fc_b       = (const float*)d_in[12];
    const float* mlpproj_w  = (const float*)d_in[13];
    const float* mlpproj_b  = (const float*)d_in[14];
    const float* lnf_g      = (const float*)d_in[15];
    const float* lnf_b      = (const float*)d_in[16];
    const float* head_w     = (const float*)d_in[17];
    const float* head_b     = (const float*)d_in[18];

    float *x, *h, *qkv, *y, *fc, *part;
    unsigned* wtf;
    cudaGetSymbolAddress((void**)&x, g_x);
    cudaGetSymbolAddress((void**)&h, g_h);
    cudaGetSymbolAddress((void**)&qkv, g_qkv);
    cudaGetSymbolAddress((void**)&y, g_y);
    cudaGetSymbolAddress((void**)&fc, g_fc);
    cudaGetSymbolAddress((void**)&part, g_part);
    cudaGetSymbolAddress((void**)&wtf, g_wtf);

    cudaFuncSetAttribute(attn_kernel, cudaFuncAttributeMaxDynamicSharedMemorySize, ATTN_SMEM);
    cudaFuncSetAttribute(attn_kernel, cudaFuncAttributePreferredSharedMemoryCarveout,
                         cudaSharedmemCarveoutMaxShared);
    cudaFuncSetAttribute(gemm_tc_kernel, cudaFuncAttributeMaxDynamicSharedMemorySize, GEMM_SMEM);
    cudaFuncSetAttribute(gemm_tc_kernel, cudaFuncAttributePreferredSharedMemoryCarveout,
                         cudaSharedmemCarveoutMaxShared);

    convert_w_kernel<<<2048, 256>>>(attn_w, attnproj_w, fc_w, mlpproj_w, wtf);
    embed_ln_kernel<<<BT / 8, 256>>>(X, wpe, ln1_g, ln1_b, x, h);
    gemm_tc_kernel<<<dim3(6, 128), 256, GEMM_SMEM>>>(h, wtf + WQo, attn_b, nullptr, qkv, BT, 768, 256, 1, 0);
    attn_kernel<<<dim3(NQT2 / 2, Bc * Hc), 256, ATTN_SMEM>>>(qkv, y);
    gemm_tc_kernel<<<dim3(2, 128), 256, GEMM_SMEM>>>(y, wtf + WPo, attnproj_b, x, x, BT, 256, 256, 0, 1);
    ln_kernel<<<BT / 8, 256>>>(x, ln2_g, ln2_b, h, 0);
    gemm_tc_kernel<<<dim3(4, 128), 256, GEMM_SMEM>>>(h, wtf + WFo, fc_b, nullptr, fc, BT, 512, 256, 1, 0);
    gemm_tc_kernel<<<dim3(2, 128), 256, GEMM_SMEM>>>(fc, wtf + WMo, mlpproj_b, x, x, BT, 256, 512, 1, 1);
    ln_kernel<<<BT / 8, 256>>>(x, lnf_g, lnf_b, h, 1);
    meanpart_kernel<<<dim3(8, Bc), 256>>>(h, part);
    final_kernel<<<1, 1024>>>(part, head_w, head_b, Y, (float*)d_out);
}